// round 4
// baseline (speedup 1.0000x reference)
#include <cuda_runtime.h>
#include <cstdint>

// Shapes (fixed by the problem): OBS*FEAT = 1536 floats per candidate,
// PRED*FEAT = 2400 floats output. N derived from in_sizes.
#define ROW_F4      384   // 1536 floats / 4
#define F4_PER_LANE 12    // 384 / 32 lanes
#define TPB         256
#define WARPS_PB    8
#define NBLOCKS     888

// Global argmin scratch: packed (float_bits(dist) << 32) | candidate_index.
// dist >= 0 so IEEE bits are monotone; low-32 index => ties pick smaller index
// (matches jnp.argmin first-occurrence).
__device__ unsigned long long g_best;

__global__ void nn_init_kernel() {
    g_best = 0xFFFFFFFFFFFFFFFFULL;
}

__global__ __launch_bounds__(TPB)
void nn_dist_kernel(const float* __restrict__ in_pose,
                    const float* __restrict__ train,
                    int N) {
    const int lane = threadIdx.x & 31;
    const int warp = threadIdx.x >> 5;

    // Query pose resident in registers: 12 x float4 per lane.
    float4 q[F4_PER_LANE];
    const float4* qp = reinterpret_cast<const float4*>(in_pose);
#pragma unroll
    for (int i = 0; i < F4_PER_LANE; i++)
        q[i] = qp[i * 32 + lane];

    unsigned long long best = 0xFFFFFFFFFFFFFFFFULL;

    const int gwarp  = blockIdx.x * WARPS_PB + warp;
    const int stride = gridDim.x * WARPS_PB;

    for (int c = gwarp; c < N; c += stride) {
        const float4* row =
            reinterpret_cast<const float4*>(train) + (size_t)c * ROW_F4;
        float acc = 0.0f;
#pragma unroll
        for (int i = 0; i < F4_PER_LANE; i++) {
            float4 v = row[i * 32 + lane];   // coalesced 512B bursts, MLP=12
            float dx = v.x - q[i].x;
            float dy = v.y - q[i].y;
            float dz = v.z - q[i].z;
            float dw = v.w - q[i].w;
            acc += dx * dx + dy * dy + dz * dz + dw * dw;
        }
        // Warp-reduce sum of squared diffs (argmin of sum == argmin of mean).
#pragma unroll
        for (int off = 16; off; off >>= 1)
            acc += __shfl_xor_sync(0xffffffffu, acc, off);

        unsigned long long key =
            ((unsigned long long)__float_as_uint(acc) << 32) | (unsigned)c;
        best = best < key ? best : key;
    }

    // Block reduce: 8 warp keys -> 1 atomic per block.
    __shared__ unsigned long long sbest[WARPS_PB];
    if (lane == 0) sbest[warp] = best;
    __syncthreads();
    if (warp == 0) {
        unsigned long long b =
            (lane < WARPS_PB) ? sbest[lane] : 0xFFFFFFFFFFFFFFFFULL;
#pragma unroll
        for (int off = 4; off; off >>= 1) {
            unsigned long long o = __shfl_xor_sync(0xffffffffu, b, off);
            b = b < o ? b : o;
        }
        if (lane == 0) atomicMin(&g_best, b);
    }
}

__global__ void nn_gather_kernel(const float* __restrict__ vels,
                                 float* __restrict__ out,
                                 int out_elems) {
    const unsigned idx = (unsigned)(g_best & 0xFFFFFFFFu);
    const float* src = vels + (size_t)idx * (size_t)out_elems;
    // out_elems = 2400, divisible by 4 -> float4 copy.
    const float4* s4 = reinterpret_cast<const float4*>(src);
    float4*       d4 = reinterpret_cast<float4*>(out);
    const int n4 = out_elems >> 2;
    for (int i = threadIdx.x; i < n4; i += blockDim.x)
        d4[i] = s4[i];
}

extern "C" void kernel_launch(void* const* d_in, const int* in_sizes, int n_in,
                              void* d_out, int out_size) {
    const float* in_pose     = (const float*)d_in[0];  // [OBS, FEAT] = 1536
    const float* train_poses = (const float*)d_in[1];  // [N, OBS, FEAT]
    const float* target_vels = (const float*)d_in[2];  // [N, PRED, FEAT]

    const int row  = in_sizes[0];          // 1536
    const int N    = in_sizes[1] / row;    // 100000
    float* out = (float*)d_out;

    nn_init_kernel<<<1, 1>>>();
    nn_dist_kernel<<<NBLOCKS, TPB>>>(in_pose, train_poses, N);
    nn_gather_kernel<<<1, 256>>>(target_vels, out, out_size);
}